// round 11
// baseline (speedup 1.0000x reference)
#include <cuda_runtime.h>
#include <cuda_fp16.h>
#include <cstring>

#define DD 64
#define NMAX 100000
#define EMAX 1200000

// Portable bit-casts
__device__ __forceinline__ unsigned h2_to_u32(__half2 h) { unsigned u; memcpy(&u, &h, 4); return u; }
__device__ __forceinline__ __half2 u32_to_h2(unsigned u) { __half2 h; memcpy(&h, &u, 4); return h; }

// Scratch (allocation-free rule: __device__ globals). 16B-aligned.
__device__ __align__(16) float  g_deg[NMAX];      // edge-weight in-degree (no self-loop)
__device__ __align__(16) float  g_dis[NMAX];      // rsqrt(1 + deg)
__device__ __align__(16) int    g_cnt[NMAX];
__device__ __align__(16) int    g_row[NMAX + 1];
__device__ __align__(16) int    g_cur[NMAX];
__device__ __align__(16) float2 g_pair[EMAX];     // (src as int bits, w * dis[src]), bucketed by dst
__device__ __align__(16) __half g_hs [NMAX * DD]; // fp16 UNSCALED h = X@W
__device__ __align__(16) float  g_x1 [NMAX * DD]; // layer-1 output (fp32)

// ---------------------------------------------------------------------------
// count in-degree + weighted degree.
__global__ void count_kernel(const int* __restrict__ ei,
                             const float* __restrict__ ew, int E) {
    int e = blockIdx.x * blockDim.x + threadIdx.x;
    if (e < E) {
        int d = ei[E + e];
        atomicAdd(&g_cnt[d], 1);
        atomicAdd(&g_deg[d], ew[e]);
    }
}

// single-block exclusive scan of g_cnt -> g_row, g_cur; dis = rsqrt(1 + deg)
__global__ __launch_bounds__(1024) void scan_dis_kernel(int n) {
    __shared__ int ssum[1024];
    int t = threadIdx.x;
    int chunk = (n + 1023) >> 10;
    int beg = t * chunk;
    int end = min(n, beg + chunk);
    int s = 0;
    for (int i = beg; i < end; i++) s += g_cnt[i];
    ssum[t] = s;
    __syncthreads();
    if (t == 0) {
        int acc = 0;
        for (int i = 0; i < 1024; i++) { int v = ssum[i]; ssum[i] = acc; acc += v; }
        g_row[n] = acc;
    }
    __syncthreads();
    int acc = ssum[t];
    for (int i = beg; i < end; i++) {
        int c = g_cnt[i];
        g_row[i] = acc;
        g_cur[i] = acc;
        acc += c;
        g_dis[i] = rsqrtf(1.0f + g_deg[i]);
    }
}

// bucket edges by dst, folding dis[src] into the weight: pair = (s, w*dis[s])
__global__ void fill_kernel(const int* __restrict__ ei,
                            const float* __restrict__ ew, int E) {
    int e = blockIdx.x * blockDim.x + threadIdx.x;
    if (e < E) {
        int s = ei[e];
        int d = ei[E + e];
        int p = atomicAdd(&g_cur[d], 1);
        g_pair[p] = make_float2(__int_as_float(s), ew[e] * g_dis[s]);
    }
}

// ---------------------------------------------------------------------------
// GEMM: h = fp16(X @ W), UNSCALED (no dis dependency -> overlappable with CSR).
// One block = 64 rows, 256 threads, 4x4 register tiles (R6 mainloop).
__global__ __launch_bounds__(256) void gemm_h_kernel(
    const float* __restrict__ Xin, const float* __restrict__ W, int n, int src_sel)
{
    __shared__ float sW[DD * DD];
    __shared__ float sX[DD * DD];

    const float* X = src_sel ? (const float*)g_x1 : Xin;

    int t = threadIdx.x;
    int row0 = blockIdx.x * 64;

    {   // W (4096 floats) coalesced as float4
        float4* sW4 = (float4*)sW;
        const float4* W4 = (const float4*)W;
        #pragma unroll
        for (int i = 0; i < 4; i++) sW4[t + i * 256] = W4[t + i * 256];
    }
    {   // X tile, zero-pad OOB rows
        float4* sX4 = (float4*)sX;
        const float4* X4 = (const float4*)X;
        if (row0 + 64 <= n) {
            #pragma unroll
            for (int i = 0; i < 4; i++) sX4[t + i * 256] = X4[(size_t)row0 * 16 + t + i * 256];
        } else {
            #pragma unroll
            for (int i = 0; i < 4; i++) {
                int idx = t + i * 256;
                int r = idx >> 4;
                float4 v = make_float4(0.f, 0.f, 0.f, 0.f);
                if (row0 + r < n) v = X4[(size_t)row0 * 16 + idx];
                sX4[idx] = v;
            }
        }
    }
    __syncthreads();

    int rg = (t >> 4) * 4;
    int c0 = (t & 15) * 4;

    float a[4][4];
    #pragma unroll
    for (int i = 0; i < 4; i++)
        #pragma unroll
        for (int j = 0; j < 4; j++) a[i][j] = 0.f;

    #pragma unroll 16
    for (int k = 0; k < 64; k++) {
        float4 wv = *(const float4*)(sW + k * 64 + c0);
        #pragma unroll
        for (int i = 0; i < 4; i++) {
            float xv = sX[(rg + i) * 64 + k];
            a[i][0] = fmaf(xv, wv.x, a[i][0]);
            a[i][1] = fmaf(xv, wv.y, a[i][1]);
            a[i][2] = fmaf(xv, wv.z, a[i][2]);
            a[i][3] = fmaf(xv, wv.w, a[i][3]);
        }
    }

    uint2* hp = (uint2*)g_hs;                       // row stride 16 (64 halves / 4-per-uint2)
    #pragma unroll
    for (int i = 0; i < 4; i++) {
        int r = row0 + rg + i;
        if (r < n) {
            __half2 h01 = __floats2half2_rn(a[i][0], a[i][1]);
            __half2 h23 = __floats2half2_rn(a[i][2], a[i][3]);
            hp[(size_t)r * 16 + (c0 >> 2)] = make_uint2(h2_to_u32(h01), h2_to_u32(h23));
        }
    }
}

// ---------------------------------------------------------------------------
// Gather-aggregate: 16 threads per node, thread q owns 4 fp16 columns (8B).
//   acc = dis[d]*h[d] (self);  acc += wp_e * h[src_e]   (wp = w*dis[s])
//   r = relu(dis[d]*acc + b)
//   mode 0: x1 = r (fp32)     mode 1: out = 0.5*(x1 + r)
// Edge loop unrolled x4: four independent 8B loads in flight per lane.
__global__ __launch_bounds__(256) void gather_kernel(
    const float* __restrict__ b, float* __restrict__ out, int n, int mode)
{
    int gid = blockIdx.x * blockDim.x + threadIdx.x;
    int d = gid >> 4;
    if (d >= n) return;
    int q = gid & 15;

    const uint2* __restrict__ hs2 = (const uint2*)g_hs;
    size_t oi = (size_t)d * 16 + q;

    float ds = g_dis[d];
    uint2 self = hs2[oi];
    float2 s01 = __half22float2(u32_to_h2(self.x));
    float2 s23 = __half22float2(u32_to_h2(self.y));
    float4 acc = make_float4(ds * s01.x, ds * s01.y, ds * s23.x, ds * s23.y);

    int beg = g_row[d];
    int end = g_row[d + 1];

    int i = beg;
    for (; i + 4 <= end; i += 4) {
        float2 p0 = g_pair[i];
        float2 p1 = g_pair[i + 1];
        float2 p2 = g_pair[i + 2];
        float2 p3 = g_pair[i + 3];
        uint2 r0 = hs2[(size_t)__float_as_int(p0.x) * 16 + q];
        uint2 r1 = hs2[(size_t)__float_as_int(p1.x) * 16 + q];
        uint2 r2 = hs2[(size_t)__float_as_int(p2.x) * 16 + q];
        uint2 r3 = hs2[(size_t)__float_as_int(p3.x) * 16 + q];
        float2 a01, a23;
        a01 = __half22float2(u32_to_h2(r0.x)); a23 = __half22float2(u32_to_h2(r0.y));
        acc.x = fmaf(p0.y, a01.x, acc.x); acc.y = fmaf(p0.y, a01.y, acc.y);
        acc.z = fmaf(p0.y, a23.x, acc.z); acc.w = fmaf(p0.y, a23.y, acc.w);
        a01 = __half22float2(u32_to_h2(r1.x)); a23 = __half22float2(u32_to_h2(r1.y));
        acc.x = fmaf(p1.y, a01.x, acc.x); acc.y = fmaf(p1.y, a01.y, acc.y);
        acc.z = fmaf(p1.y, a23.x, acc.z); acc.w = fmaf(p1.y, a23.y, acc.w);
        a01 = __half22float2(u32_to_h2(r2.x)); a23 = __half22float2(u32_to_h2(r2.y));
        acc.x = fmaf(p2.y, a01.x, acc.x); acc.y = fmaf(p2.y, a01.y, acc.y);
        acc.z = fmaf(p2.y, a23.x, acc.z); acc.w = fmaf(p2.y, a23.y, acc.w);
        a01 = __half22float2(u32_to_h2(r3.x)); a23 = __half22float2(u32_to_h2(r3.y));
        acc.x = fmaf(p3.y, a01.x, acc.x); acc.y = fmaf(p3.y, a01.y, acc.y);
        acc.z = fmaf(p3.y, a23.x, acc.z); acc.w = fmaf(p3.y, a23.y, acc.w);
    }
    for (; i < end; i++) {
        float2 p0 = g_pair[i];
        uint2 r0 = hs2[(size_t)__float_as_int(p0.x) * 16 + q];
        float2 a01 = __half22float2(u32_to_h2(r0.x));
        float2 a23 = __half22float2(u32_to_h2(r0.y));
        acc.x = fmaf(p0.y, a01.x, acc.x); acc.y = fmaf(p0.y, a01.y, acc.y);
        acc.z = fmaf(p0.y, a23.x, acc.z); acc.w = fmaf(p0.y, a23.y, acc.w);
    }

    float4 bb = ((const float4*)b)[q];
    float4 r;
    r.x = fmaxf(fmaf(ds, acc.x, bb.x), 0.f);
    r.y = fmaxf(fmaf(ds, acc.y, bb.y), 0.f);
    r.z = fmaxf(fmaf(ds, acc.z, bb.z), 0.f);
    r.w = fmaxf(fmaf(ds, acc.w, bb.w), 0.f);

    if (mode == 0) {
        ((float4*)g_x1)[oi] = r;
    } else {
        float4 x1v = ((const float4*)g_x1)[oi];
        r.x = 0.5f * (x1v.x + r.x);
        r.y = 0.5f * (x1v.y + r.y);
        r.z = 0.5f * (x1v.z + r.z);
        r.w = 0.5f * (x1v.w + r.w);
        ((float4*)out)[oi] = r;
    }
}

// ---------------------------------------------------------------------------
extern "C" void kernel_launch(void* const* d_in, const int* in_sizes, int n_in,
                              void* d_out, int out_size) {
    const float* x  = (const float*)d_in[0];
    const int*   ei = (const int*)d_in[1];      // int32 (JAX default x64-disabled)
    const float* ew = (const float*)d_in[2];
    const float* W1 = (const float*)d_in[3];
    const float* b1 = (const float*)d_in[4];
    const float* W2 = (const float*)d_in[5];
    const float* b2 = (const float*)d_in[6];
    float* out = (float*)d_out;

    int n = in_sizes[0] / DD;      // 100000
    int E = in_sizes[2];           // 1200000

    int nb_e   = (E + 255) / 256;
    int nb_gat = (int)(((long long)n * 16 + 255) / 256);
    int nb_g   = (n + 63) / 64;

    // One-time host resources (no device memory involved).
    static cudaStream_t s2 = nullptr;
    static cudaEvent_t ev_fork = nullptr, ev_join = nullptr;
    if (!s2) {
        cudaStreamCreateWithFlags(&s2, cudaStreamNonBlocking);
        cudaEventCreateWithFlags(&ev_fork, cudaEventDisableTiming);
        cudaEventCreateWithFlags(&ev_join, cudaEventDisableTiming);
    }

    void* p_cnt = nullptr; void* p_deg = nullptr;
    cudaGetSymbolAddress(&p_cnt, g_cnt);
    cudaGetSymbolAddress(&p_deg, g_deg);

    // ---- fork: GEMM1 on s2, CSR build on the capture (default) stream ----
    cudaEventRecord(ev_fork, 0);
    cudaStreamWaitEvent(s2, ev_fork, 0);
    gemm_h_kernel<<<nb_g, 256, 0, s2>>>(x, W1, n, 0);          // h1 = X@W1 (unscaled)
    cudaEventRecord(ev_join, s2);

    cudaMemsetAsync(p_cnt, 0, (size_t)n * sizeof(int), 0);
    cudaMemsetAsync(p_deg, 0, (size_t)n * sizeof(float), 0);
    count_kernel<<<nb_e, 256>>>(ei, ew, E);
    scan_dis_kernel<<<1, 1024>>>(n);                            // dis = rsqrt(1+deg)
    fill_kernel<<<nb_e, 256>>>(ei, ew, E);                      // wp = w * dis[src]

    // ---- join, then serial tail ----
    cudaStreamWaitEvent(0, ev_join, 0);
    gather_kernel<<<nb_gat, 256>>>(b1, out, n, 0);              // writes g_x1
    gemm_h_kernel<<<nb_g, 256>>>(x, W2, n, 1);                  // h2 = x1@W2 (unscaled)
    gather_kernel<<<nb_gat, 256>>>(b2, out, n, 1);              // out = 0.5*(x1+x2)
}